// round 14
// baseline (speedup 1.0000x reference)
#include <cuda_runtime.h>
#include <cuda_bf16.h>
#include <stdint.h>

#define THREADS 512
#define PTS     64
#define HID     128
#define DIMX    39
#define NHID    6

// padded row stride (bytes) for A (256 rows): 128 bf16 + 8 pad
#define ASTR    272u

// smem byte offsets (A only + small constants)
#define B_AHI   0u
#define B_ALO   69632u      // 256*272
#define B_BIAS  139264u     // 7 x 128 f32 (input + 6 hidden)
#define B_WW    142848u     // 3x128 f32
#define B_WV    144384u
#define B_BH    145920u     // bw[3], bv[3]
#define SMEM_BYTES 145952u

// W fragments, pre-split to bf16 hi/lo in ldmatrix per-lane order.
// flat = (layer*2+wn)*2048 + ks*256 + (np*2+h)*32 + lane   (uint4 each)
__device__ uint4 g_fragW[24576];    // 6 layers * 2 wn * 2048
__device__ uint4 g_fragWin[1536];   // 2 wn * 3 ks * 256

// ---------------------------------------------------------------- PTX helpers
static __device__ __forceinline__ uint32_t smem_u32(const void* p){
    uint32_t a;
    asm("{ .reg .u64 t; cvta.to.shared.u64 t, %1; cvt.u32.u64 %0, t; }" : "=r"(a) : "l"(p));
    return a;
}
static __device__ __forceinline__ void ldsm4(uint32_t* r, uint32_t addr){
    asm volatile("ldmatrix.sync.aligned.m8n8.x4.shared.b16 {%0,%1,%2,%3}, [%4];"
        : "=r"(r[0]), "=r"(r[1]), "=r"(r[2]), "=r"(r[3]) : "r"(addr));
}
static __device__ __forceinline__ void mma16816(float* d, const uint32_t* a,
                                                uint32_t b0, uint32_t b1){
    asm volatile("mma.sync.aligned.m16n8k16.row.col.f32.bf16.bf16.f32 "
        "{%0,%1,%2,%3}, {%4,%5,%6,%7}, {%8,%9}, {%0,%1,%2,%3};"
        : "+f"(d[0]), "+f"(d[1]), "+f"(d[2]), "+f"(d[3])
        : "r"(a[0]), "r"(a[1]), "r"(a[2]), "r"(a[3]), "r"(b0), "r"(b1));
}

// split fp32 pair -> packed bf16 hi pair + lo pair
static __device__ __forceinline__ void split2(float f0, float f1, uint32_t& hp, uint32_t& lp){
    __nv_bfloat162 h = __floats2bfloat162_rn(f0, f1);
    hp = *(uint32_t*)&h;
    float fh0 = __uint_as_float(hp << 16);
    float fh1 = __uint_as_float(hp & 0xffff0000u);
    __nv_bfloat162 l = __floats2bfloat162_rn(f0 - fh0, f1 - fh1);
    lp = *(uint32_t*)&l;
}
static __device__ __forceinline__ void split_bf16(float v, __nv_bfloat16& h, __nv_bfloat16& l){
    h = __float2bfloat16(v);
    l = __float2bfloat16(v - __bfloat162float(h));
}
__device__ __forceinline__ float bflo(uint32_t u){ return __uint_as_float(u << 16); }
__device__ __forceinline__ float bfhi(uint32_t u){ return __uint_as_float(u & 0xffff0000u); }

// ---------------------------------------------------------------- dual numbers
struct Dn { float v, x, y, z; };
__device__ __forceinline__ Dn dmk(float v){ return Dn{v,0.f,0.f,0.f}; }
__device__ __forceinline__ Dn dadd(const Dn&a,const Dn&b){ return Dn{a.v+b.v,a.x+b.x,a.y+b.y,a.z+b.z}; }
__device__ __forceinline__ Dn dsub(const Dn&a,const Dn&b){ return Dn{a.v-b.v,a.x-b.x,a.y-b.y,a.z-b.z}; }
__device__ __forceinline__ Dn dneg(const Dn&a){ return Dn{-a.v,-a.x,-a.y,-a.z}; }
__device__ __forceinline__ Dn dmul(const Dn&a,const Dn&b){
    return Dn{a.v*b.v, fmaf(a.v,b.x,a.x*b.v), fmaf(a.v,b.y,a.y*b.v), fmaf(a.v,b.z,a.z*b.v)};
}
__device__ __forceinline__ Dn dsqrt(const Dn&a){ float s=sqrtf(a.v),h=0.5f/s; return Dn{s,a.x*h,a.y*h,a.z*h}; }
__device__ __forceinline__ Dn drcp(const Dn&a){ float r=1.f/a.v,m=-r*r; return Dn{r,a.x*m,a.y*m,a.z*m}; }
__device__ __forceinline__ Dn dsin(const Dn&a){ float s=sinf(a.v),c=cosf(a.v); return Dn{s,c*a.x,c*a.y,c*a.z}; }
__device__ __forceinline__ Dn dcos(const Dn&a){ float s=sinf(a.v),c=cosf(a.v); return Dn{c,-s*a.x,-s*a.y,-s*a.z}; }

// ---------------------------------------------------------------- prep kernel: W -> fragment-ordered bf16 hi/lo
// fragment reg i of lane l (warp wn, tile np, kstep ks):
//   j = wn*64 + np*16 + (l>>2) + ((i>>1)&1)*8
//   k = ks*16 + (i&1)*8 + 2*(l&3)      (pair k, k+1)
__global__ void prep_kernel(const float* __restrict__ Win, const float* __restrict__ Ws)
{
    int f = blockIdx.x * blockDim.x + threadIdx.x;
    if (f < 24576) {
        int lane = f & 31, h = (f >> 5) & 1, np = (f >> 6) & 3;
        int ks = (f >> 8) & 7, wn = (f >> 11) & 1, l = f >> 12;
        const float* W = Ws + (size_t)l * HID * HID;
        uint32_t r[4];
        #pragma unroll
        for (int i = 0; i < 4; ++i) {
            int j = wn * 64 + np * 16 + (lane >> 2) + ((i >> 1) & 1) * 8;
            int k = ks * 16 + (i & 1) * 8 + 2 * (lane & 3);
            float w0 = W[j * HID + k], w1 = W[j * HID + k + 1];
            uint32_t hp, lp;
            split2(w0, w1, hp, lp);
            r[i] = h ? lp : hp;
        }
        g_fragW[f] = make_uint4(r[0], r[1], r[2], r[3]);
    } else if (f < 24576 + 1536) {
        int f2 = f - 24576;
        int lane = f2 & 31, h = (f2 >> 5) & 1, np = (f2 >> 6) & 3;
        int ks = (f2 >> 8) % 3, wn = (f2 >> 8) / 3;
        uint32_t r[4];
        #pragma unroll
        for (int i = 0; i < 4; ++i) {
            int j = wn * 64 + np * 16 + (lane >> 2) + ((i >> 1) & 1) * 8;
            int k = ks * 16 + (i & 1) * 8 + 2 * (lane & 3);
            float w0 = (k     < DIMX) ? Win[j * DIMX + k]     : 0.f;
            float w1 = (k + 1 < DIMX) ? Win[j * DIMX + k + 1] : 0.f;
            uint32_t hp, lp;
            split2(w0, w1, hp, lp);
            r[i] = h ? lp : hp;
        }
        g_fragWin[f2] = make_uint4(r[0], r[1], r[2], r[3]);
    }
}

// ---------------------------------------------------------------- one MLP layer: B frags via LDG, A via LDSM
template<int NK>
__device__ __forceinline__ void layer_mma(char* smem, uint32_t sb,
                                          const uint4* __restrict__ frag,
                                          const float* __restrict__ sBias,
                                          int wid, int lane, float slope)
{
    const int wm = wid >> 1, wn = wid & 1;
    const int c0 = wm * 32, n0 = wn * 64;
    const int q  = lane >> 3, rr = lane & 7;

    float acc[2][8][4];
    #pragma unroll
    for (int m = 0; m < 2; ++m)
        #pragma unroll
        for (int nt = 0; nt < 8; ++nt)
            #pragma unroll
            for (int i = 0; i < 4; ++i) acc[m][nt][i] = 0.f;

    const uint32_t a_base = sb + B_AHI
        + (uint32_t)(c0 + rr + 8 * (q & 1)) * ASTR + (uint32_t)(q >> 1) * 16u;
    const uint4* fl = frag + lane;

    #pragma unroll
    for (int ks = 0; ks < NK; ++ks) {
        // B fragments: 8 independent LDG.128 (L2-resident), issued first
        const uint4* fp = fl + ks * 256;
        uint4 bh0 = fp[0],   bh1 = fp[64],  bh2 = fp[128], bh3 = fp[192];
        uint4 bl0 = fp[32],  bl1 = fp[96],  bl2 = fp[160], bl3 = fp[224];

        uint32_t ah[2][4], al[2][4];
        uint32_t aa = a_base + (uint32_t)ks * 32u;
        ldsm4(ah[0], aa);
        ldsm4(ah[1], aa + 16u * ASTR);
        ldsm4(al[0], aa + (B_ALO - B_AHI));
        ldsm4(al[1], aa + 16u * ASTR + (B_ALO - B_AHI));

        // term 1: Ahi*Whi, term 2: Alo*Whi
        #pragma unroll
        for (int m = 0; m < 2; ++m) {
            mma16816(acc[m][0], ah[m], bh0.x, bh0.y);
            mma16816(acc[m][1], ah[m], bh0.z, bh0.w);
            mma16816(acc[m][2], ah[m], bh1.x, bh1.y);
            mma16816(acc[m][3], ah[m], bh1.z, bh1.w);
            mma16816(acc[m][4], ah[m], bh2.x, bh2.y);
            mma16816(acc[m][5], ah[m], bh2.z, bh2.w);
            mma16816(acc[m][6], ah[m], bh3.x, bh3.y);
            mma16816(acc[m][7], ah[m], bh3.z, bh3.w);
        }
        #pragma unroll
        for (int m = 0; m < 2; ++m) {
            mma16816(acc[m][0], al[m], bh0.x, bh0.y);
            mma16816(acc[m][1], al[m], bh0.z, bh0.w);
            mma16816(acc[m][2], al[m], bh1.x, bh1.y);
            mma16816(acc[m][3], al[m], bh1.z, bh1.w);
            mma16816(acc[m][4], al[m], bh2.x, bh2.y);
            mma16816(acc[m][5], al[m], bh2.z, bh2.w);
            mma16816(acc[m][6], al[m], bh3.x, bh3.y);
            mma16816(acc[m][7], al[m], bh3.z, bh3.w);
        }
        // term 3: Ahi*Wlo
        #pragma unroll
        for (int m = 0; m < 2; ++m) {
            mma16816(acc[m][0], ah[m], bl0.x, bl0.y);
            mma16816(acc[m][1], ah[m], bl0.z, bl0.w);
            mma16816(acc[m][2], ah[m], bl1.x, bl1.y);
            mma16816(acc[m][3], ah[m], bl1.z, bl1.w);
            mma16816(acc[m][4], ah[m], bl2.x, bl2.y);
            mma16816(acc[m][5], ah[m], bl2.z, bl2.w);
            mma16816(acc[m][6], ah[m], bl3.x, bl3.y);
            mma16816(acc[m][7], ah[m], bl3.z, bl3.w);
        }
    }

    __syncthreads();   // all mma reads of A complete before in-place A writes

    // epilogue: bias + (leaky)relu with value-row gating, split to bf16, store to A
    const int comp = (lane >> 2) & 3;
    const int vl   = lane & 19;
    const int colq = 2 * (lane & 3);

    #pragma unroll
    for (int m = 0; m < 2; ++m) {
        #pragma unroll
        for (int nt = 0; nt < 8; ++nt) {
            float* d = acc[m][nt];
            int j0 = n0 + nt * 8 + colq;
            float b0 = sBias[j0], b1 = sBias[j0 + 1];
            float q0 = d[0] + b0, q1 = d[1] + b1;
            float q2 = d[2] + b0, q3 = d[3] + b1;
            float m0 = __shfl_sync(0xffffffffu, q0, vl) > 0.f ? 1.f : slope;
            float m1 = __shfl_sync(0xffffffffu, q1, vl) > 0.f ? 1.f : slope;
            float m2 = __shfl_sync(0xffffffffu, q2, vl) > 0.f ? 1.f : slope;
            float m3 = __shfl_sync(0xffffffffu, q3, vl) > 0.f ? 1.f : slope;
            float o0 = m0 * (comp == 0 ? q0 : d[0]);
            float o1 = m1 * (comp == 0 ? q1 : d[1]);
            float o2 = m2 * (comp == 0 ? q2 : d[2]);
            float o3 = m3 * (comp == 0 ? q3 : d[3]);
            uint32_t h01, l01, h23, l23;
            split2(o0, o1, h01, l01);
            split2(o2, o3, h23, l23);
            uint32_t cA  = (uint32_t)(c0 + m * 16 + (lane >> 2));
            uint32_t off = cA * ASTR + (uint32_t)j0 * 2u;
            *(uint32_t*)(smem + B_AHI + off) = h01;
            *(uint32_t*)(smem + B_ALO + off) = l01;
            off += 8u * ASTR;
            *(uint32_t*)(smem + B_AHI + off) = h23;
            *(uint32_t*)(smem + B_ALO + off) = l23;
        }
    }
}

// ----------------------------------------------------------------
__global__ __launch_bounds__(THREADS, 1)
void nerfies_kernel(const float* __restrict__ x,
                    const float* __restrict__ bin,
                    const float* __restrict__ bs,
                    const float* __restrict__ Ww,
                    const float* __restrict__ bw,
                    const float* __restrict__ Wv,
                    const float* __restrict__ bv,
                    const int*   __restrict__ iter,
                    float* __restrict__ out,
                    int N)
{
    extern __shared__ __align__(16) char smem[];
    const uint32_t sb = smem_u32(smem);
    const int tid  = threadIdx.x;
    const int wid  = tid >> 5;
    const int lane = tid & 31;
    const int p0   = blockIdx.x * PTS;
    const int wn   = wid & 1;

    // zero A (hi+lo) regions (covers k-padding)
    {
        uint4 z = make_uint4(0, 0, 0, 0);
        for (uint32_t o = (uint32_t)tid * 16u; o < B_BIAS; o += THREADS * 16u)
            *(uint4*)(smem + o) = z;
    }

    // posenc (PI literal 3.14, N_ANNEAL = 3000, M=6, K0=-3)
    const float itf = (float)(*iter);
    const float aa  = 6.0f * itf / 3000.0f;
    __syncthreads();

    for (int idx = tid; idx < PTS * DIMX; idx += THREADS) {
        int p = idx / DIMX, f = idx % DIMX;
        int gp = p0 + p;
        float val = 0.f, d0 = 0.f, d1 = 0.f, d2 = 0.f;
        if (gp < N) {
            if (f < 3) {
                val = x[gp * 3 + f];
                if (f == 0) d0 = 1.f; else if (f == 1) d1 = 1.f; else d2 = 1.f;
            } else {
                int g = f - 3;
                int cdim = g / 12;
                int rem = g % 12;
                int t = rem / 6;
                int j = rem % 6;
                float wj = (1.0f - cosf(fminf(fmaxf(aa - (float)j, 0.f), 1.f) * 3.14f)) * 0.5f;
                float mj = exp2f((float)(j - 3)) * 3.14f;
                float xc = x[gp * 3 + cdim];
                float ang = xc * mj;
                float sv = sinf(ang), cv = cosf(ang);
                float dv;
                if (t == 0) { val = sv * wj; dv =  cv * mj * wj; }
                else        { val = cv * wj; dv = -sv * mj * wj; }
                if (cdim == 0) d0 = dv; else if (cdim == 1) d1 = dv; else d2 = dv;
            }
        }
        float vals[4] = {val, d0, d1, d2};
        #pragma unroll
        for (int d = 0; d < 4; ++d) {
            __nv_bfloat16 hh, ll;
            split_bf16(vals[d], hh, ll);
            uint32_t off = (uint32_t)(4 * p + d) * ASTR + (uint32_t)f * 2u;
            *(__nv_bfloat16*)(smem + B_AHI + off) = hh;
            *(__nv_bfloat16*)(smem + B_ALO + off) = ll;
        }
    }

    // all biases (input + 6 hidden) preloaded once
    for (int i = tid; i < 896; i += THREADS) {
        float v = (i < 128) ? bin[i] : bs[i - 128];
        ((float*)(smem + B_BIAS))[i] = v;
    }
    // head weights + biases
    for (int idx = tid; idx < 384; idx += THREADS) {
        ((float*)(smem + B_WW))[idx] = Ww[idx];
        ((float*)(smem + B_WV))[idx] = Wv[idx];
    }
    if (tid < 3) {
        ((float*)(smem + B_BH))[tid]     = bw[tid];
        ((float*)(smem + B_BH))[tid + 3] = bv[tid];
    }
    __syncthreads();

    // ---- layer 0: K padded 39->48 (3 ksteps), leaky_relu(0.01)
    layer_mma<3>(smem, sb, g_fragWin + wn * 768,
                 (const float*)(smem + B_BIAS), wid, lane, 0.01f);

    // ---- 6 hidden layers: K=128 (8 ksteps), relu
    for (int l = 0; l < NHID; ++l) {
        __syncthreads();   // epilogue A writes visible before next MMA reads
        layer_mma<8>(smem, sb, g_fragW + (size_t)(l * 2 + wn) * 2048,
                     (const float*)(smem + B_BIAS) + (1 + l) * 128, wid, lane, 0.f);
    }
    __syncthreads();       // final A writes visible to tail

    // ---- tail: heads (128->3 x2 with tangents), SE(3) exp, outputs ----
    const float* sWw = (const float*)(smem + B_WW);
    const float* sWv = (const float*)(smem + B_WV);
    const float* sBH = (const float*)(smem + B_BH);

    const int p  = tid >> 3;
    const int r  = tid & 7;
    const int gp = p0 + p;

    float aw[3][4], av[3][4];
    #pragma unroll
    for (int a = 0; a < 3; ++a)
        #pragma unroll
        for (int cc = 0; cc < 4; ++cc) { aw[a][cc] = 0.f; av[a][cc] = 0.f; }

    #pragma unroll
    for (int kc = 0; kc < 2; ++kc) {
        int k0 = r * 16 + kc * 8;
        float f[4][8];
        #pragma unroll
        for (int c4 = 0; c4 < 4; ++c4) {
            uint32_t off = (uint32_t)(4 * p + c4) * ASTR + (uint32_t)k0 * 2u;
            uint4 hh = *(const uint4*)(smem + B_AHI + off);
            uint4 ll = *(const uint4*)(smem + B_ALO + off);
            uint32_t hu[4] = {hh.x, hh.y, hh.z, hh.w};
            uint32_t lu[4] = {ll.x, ll.y, ll.z, ll.w};
            #pragma unroll
            for (int t = 0; t < 4; ++t) {
                f[c4][2*t]   = bflo(hu[t]) + bflo(lu[t]);
                f[c4][2*t+1] = bfhi(hu[t]) + bfhi(lu[t]);
            }
        }
        #pragma unroll
        for (int i = 0; i < 8; ++i) {
            int k = k0 + i;
            #pragma unroll
            for (int a = 0; a < 3; ++a) {
                float ww = sWw[a * HID + k];
                float wv = sWv[a * HID + k];
                #pragma unroll
                for (int cc = 0; cc < 4; ++cc) {
                    aw[a][cc] = fmaf(ww, f[cc][i], aw[a][cc]);
                    av[a][cc] = fmaf(wv, f[cc][i], av[a][cc]);
                }
            }
        }
    }
    #pragma unroll
    for (int off8 = 4; off8 >= 1; off8 >>= 1) {
        #pragma unroll
        for (int a = 0; a < 3; ++a)
            #pragma unroll
            for (int cc = 0; cc < 4; ++cc) {
                aw[a][cc] += __shfl_down_sync(0xffffffffu, aw[a][cc], off8, 8);
                av[a][cc] += __shfl_down_sync(0xffffffffu, av[a][cc], off8, 8);
            }
    }

    if (r == 0 && gp < N) {
        Dn wr[3], vr[3];
        #pragma unroll
        for (int a = 0; a < 3; ++a) {
            wr[a] = Dn{aw[a][0] + sBH[a],     aw[a][1], aw[a][2], aw[a][3]};
            vr[a] = Dn{av[a][0] + sBH[a + 3], av[a][1], av[a][2], av[a][3]};
        }
        Dn n2 = dadd(dadd(dmul(wr[0], wr[0]), dmul(wr[1], wr[1])), dmul(wr[2], wr[2]));
        Dn th = dsqrt(n2);
        Dn rt = drcp(th);
        Dn w0 = dmul(wr[0], rt), w1 = dmul(wr[1], rt), w2 = dmul(wr[2], rt);
        Dn v0 = dmul(vr[0], rt), v1 = dmul(vr[1], rt), v2 = dmul(vr[2], rt);
        Dn s  = dsin(th), c = dcos(th);
        Dn oc = dsub(dmk(1.f), c);
        Dn ts = dsub(th, s);

        Dn Wm[3][3] = {
            { dmk(0.f), dneg(w2),  w1       },
            { w2,       dmk(0.f),  dneg(w0) },
            { dneg(w1), w0,        dmk(0.f) } };
        Dn W2[3][3];
        #pragma unroll
        for (int i = 0; i < 3; ++i)
            #pragma unroll
            for (int j = 0; j < 3; ++j)
                W2[i][j] = dadd(dadd(dmul(Wm[i][0], Wm[0][j]),
                                     dmul(Wm[i][1], Wm[1][j])),
                                dmul(Wm[i][2], Wm[2][j]));
        Dn R[3][3], G[3][3];
        #pragma unroll
        for (int i = 0; i < 3; ++i)
            #pragma unroll
            for (int j = 0; j < 3; ++j) {
                Dn rr2 = dadd(dmul(s, Wm[i][j]), dmul(oc, W2[i][j]));
                if (i == j) rr2.v += 1.f;
                R[i][j] = rr2;
                Dn gg = dadd(dmul(oc, Wm[i][j]), dmul(ts, W2[i][j]));
                if (i == j) gg = dadd(gg, th);
                G[i][j] = gg;
            }
        Dn tvec[3];
        #pragma unroll
        for (int i = 0; i < 3; ++i)
            tvec[i] = dadd(dadd(dmul(G[i][0], v0), dmul(G[i][1], v1)), dmul(G[i][2], v2));

        float xv0 = x[gp * 3 + 0], xv1 = x[gp * 3 + 1], xv2 = x[gp * 3 + 2];
        Dn xd[3] = { Dn{xv0, 1.f, 0.f, 0.f}, Dn{xv1, 0.f, 1.f, 0.f}, Dn{xv2, 0.f, 0.f, 1.f} };

        float* J = out + (size_t)N * 3 + (size_t)gp * 9;
        #pragma unroll
        for (int i = 0; i < 3; ++i) {
            Dn o = dadd(tvec[i],
                        dadd(dadd(dmul(R[i][0], xd[0]), dmul(R[i][1], xd[1])),
                             dmul(R[i][2], xd[2])));
            out[gp * 3 + i] = o.v;
            J[i * 3 + 0] = o.x;
            J[i * 3 + 1] = o.y;
            J[i * 3 + 2] = o.z;
        }
    }
}

// ----------------------------------------------------------------
extern "C" void kernel_launch(void* const* d_in, const int* in_sizes, int n_in,
                              void* d_out, int out_size) {
    const float* x   = (const float*)d_in[0];
    const float* Win = (const float*)d_in[1];
    const float* bin = (const float*)d_in[2];
    const float* Ws  = (const float*)d_in[3];
    const float* bs  = (const float*)d_in[4];
    const float* Ww  = (const float*)d_in[5];
    const float* bw  = (const float*)d_in[6];
    const float* Wv  = (const float*)d_in[7];
    const float* bv  = (const float*)d_in[8];
    const int*   it  = (const int*)d_in[9];
    float* out = (float*)d_out;

    int N = in_sizes[0] / 3;
    int grid = (N + PTS - 1) / PTS;

    prep_kernel<<<(24576 + 1536 + 255) / 256, 256>>>(Win, Ws);

    cudaFuncSetAttribute(nerfies_kernel,
                         cudaFuncAttributeMaxDynamicSharedMemorySize, SMEM_BYTES);
    nerfies_kernel<<<grid, THREADS, SMEM_BYTES>>>(x, bin, bs, Ww, bw, Wv, bv,
                                                  it, out, N);
}

// round 15
// speedup vs baseline: 1.5526x; 1.5526x over previous
#include <cuda_runtime.h>
#include <cuda_bf16.h>
#include <stdint.h>

#define THREADS 512
#define PTS     64
#define HID     128
#define DIMX    39
#define NHID    6

// padded row stride (bytes) for A (256 rows): 128 bf16 + 8 pad
#define ASTR    272u

// smem byte offsets (A only + small constants)
#define B_AHI   0u
#define B_ALO   69632u      // 256*272
#define B_BIAS  139264u     // 7 x 128 f32 (input + 6 hidden)
#define B_WW    142848u     // 3x128 f32
#define B_WV    144384u
#define B_BH    145920u     // bw[3], bv[3]
#define SMEM_BYTES 145952u

// W fragments, pre-split to bf16 hi/lo in ldmatrix per-lane order.
// flat = (layer*2+wn)*2048 + ks*256 + (np*2+h)*32 + lane   (uint4 each)
__device__ uint4 g_fragW[24576];    // 6 layers * 2 wn * 2048
__device__ uint4 g_fragWin[1536];   // 2 wn * 3 ks * 256

// ---------------------------------------------------------------- PTX helpers
static __device__ __forceinline__ uint32_t smem_u32(const void* p){
    uint32_t a;
    asm("{ .reg .u64 t; cvta.to.shared.u64 t, %1; cvt.u32.u64 %0, t; }" : "=r"(a) : "l"(p));
    return a;
}
static __device__ __forceinline__ void ldsm4(uint32_t* r, uint32_t addr){
    asm volatile("ldmatrix.sync.aligned.m8n8.x4.shared.b16 {%0,%1,%2,%3}, [%4];"
        : "=r"(r[0]), "=r"(r[1]), "=r"(r[2]), "=r"(r[3]) : "r"(addr));
}
static __device__ __forceinline__ void mma16816(float* d, const uint32_t* a,
                                                uint32_t b0, uint32_t b1){
    asm volatile("mma.sync.aligned.m16n8k16.row.col.f32.bf16.bf16.f32 "
        "{%0,%1,%2,%3}, {%4,%5,%6,%7}, {%8,%9}, {%0,%1,%2,%3};"
        : "+f"(d[0]), "+f"(d[1]), "+f"(d[2]), "+f"(d[3])
        : "r"(a[0]), "r"(a[1]), "r"(a[2]), "r"(a[3]), "r"(b0), "r"(b1));
}

// split fp32 pair -> packed bf16 hi pair + lo pair
static __device__ __forceinline__ void split2(float f0, float f1, uint32_t& hp, uint32_t& lp){
    __nv_bfloat162 h = __floats2bfloat162_rn(f0, f1);
    hp = *(uint32_t*)&h;
    float fh0 = __uint_as_float(hp << 16);
    float fh1 = __uint_as_float(hp & 0xffff0000u);
    __nv_bfloat162 l = __floats2bfloat162_rn(f0 - fh0, f1 - fh1);
    lp = *(uint32_t*)&l;
}
static __device__ __forceinline__ void split_bf16(float v, __nv_bfloat16& h, __nv_bfloat16& l){
    h = __float2bfloat16(v);
    l = __float2bfloat16(v - __bfloat162float(h));
}
__device__ __forceinline__ float bflo(uint32_t u){ return __uint_as_float(u << 16); }
__device__ __forceinline__ float bfhi(uint32_t u){ return __uint_as_float(u & 0xffff0000u); }

// ---------------------------------------------------------------- dual numbers
struct Dn { float v, x, y, z; };
__device__ __forceinline__ Dn dmk(float v){ return Dn{v,0.f,0.f,0.f}; }
__device__ __forceinline__ Dn dadd(const Dn&a,const Dn&b){ return Dn{a.v+b.v,a.x+b.x,a.y+b.y,a.z+b.z}; }
__device__ __forceinline__ Dn dsub(const Dn&a,const Dn&b){ return Dn{a.v-b.v,a.x-b.x,a.y-b.y,a.z-b.z}; }
__device__ __forceinline__ Dn dneg(const Dn&a){ return Dn{-a.v,-a.x,-a.y,-a.z}; }
__device__ __forceinline__ Dn dmul(const Dn&a,const Dn&b){
    return Dn{a.v*b.v, fmaf(a.v,b.x,a.x*b.v), fmaf(a.v,b.y,a.y*b.v), fmaf(a.v,b.z,a.z*b.v)};
}
__device__ __forceinline__ Dn dsqrt(const Dn&a){ float s=sqrtf(a.v),h=0.5f/s; return Dn{s,a.x*h,a.y*h,a.z*h}; }
__device__ __forceinline__ Dn drcp(const Dn&a){ float r=1.f/a.v,m=-r*r; return Dn{r,a.x*m,a.y*m,a.z*m}; }
__device__ __forceinline__ Dn dsin(const Dn&a){ float s=sinf(a.v),c=cosf(a.v); return Dn{s,c*a.x,c*a.y,c*a.z}; }
__device__ __forceinline__ Dn dcos(const Dn&a){ float s=sinf(a.v),c=cosf(a.v); return Dn{c,-s*a.x,-s*a.y,-s*a.z}; }

// ---------------------------------------------------------------- prep kernel: W -> fragment-ordered bf16 hi/lo
// fragment reg i of lane l (warp wn, tile np, kstep ks):
//   j = wn*64 + np*16 + (l>>2) + ((i>>1)&1)*8
//   k = ks*16 + (i&1)*8 + 2*(l&3)      (pair k, k+1)
__global__ void prep_kernel(const float* __restrict__ Win, const float* __restrict__ Ws)
{
    int f = blockIdx.x * blockDim.x + threadIdx.x;
    if (f < 24576) {
        int lane = f & 31, h = (f >> 5) & 1, np = (f >> 6) & 3;
        int ks = (f >> 8) & 7, wn = (f >> 11) & 1, l = f >> 12;
        const float* W = Ws + (size_t)l * HID * HID;
        uint32_t r[4];
        #pragma unroll
        for (int i = 0; i < 4; ++i) {
            int j = wn * 64 + np * 16 + (lane >> 2) + ((i >> 1) & 1) * 8;
            int k = ks * 16 + (i & 1) * 8 + 2 * (lane & 3);
            float w0 = W[j * HID + k], w1 = W[j * HID + k + 1];
            uint32_t hp, lp;
            split2(w0, w1, hp, lp);
            r[i] = h ? lp : hp;
        }
        g_fragW[f] = make_uint4(r[0], r[1], r[2], r[3]);
    } else if (f < 24576 + 1536) {
        int f2 = f - 24576;
        int lane = f2 & 31, h = (f2 >> 5) & 1, np = (f2 >> 6) & 3;
        int ks = (f2 >> 8) % 3, wn = (f2 >> 8) / 3;
        uint32_t r[4];
        #pragma unroll
        for (int i = 0; i < 4; ++i) {
            int j = wn * 64 + np * 16 + (lane >> 2) + ((i >> 1) & 1) * 8;
            int k = ks * 16 + (i & 1) * 8 + 2 * (lane & 3);
            float w0 = (k     < DIMX) ? Win[j * DIMX + k]     : 0.f;
            float w1 = (k + 1 < DIMX) ? Win[j * DIMX + k + 1] : 0.f;
            uint32_t hp, lp;
            split2(w0, w1, hp, lp);
            r[i] = h ? lp : hp;
        }
        g_fragWin[f2] = make_uint4(r[0], r[1], r[2], r[3]);
    }
}

// ---------------------------------------------------------------- one MLP layer: B frags via LDG, A via LDSM
template<int NK>
__device__ __forceinline__ void layer_mma(char* smem, uint32_t sb,
                                          const uint4* __restrict__ frag,
                                          const float* __restrict__ sBias,
                                          int wid, int lane, float slope)
{
    const int wm = wid >> 1, wn = wid & 1;
    const int c0 = wm * 32, n0 = wn * 64;
    const int q  = lane >> 3, rr = lane & 7;

    float acc[2][8][4];
    #pragma unroll
    for (int m = 0; m < 2; ++m)
        #pragma unroll
        for (int nt = 0; nt < 8; ++nt)
            #pragma unroll
            for (int i = 0; i < 4; ++i) acc[m][nt][i] = 0.f;

    const uint32_t a_base = sb + B_AHI
        + (uint32_t)(c0 + rr + 8 * (q & 1)) * ASTR + (uint32_t)(q >> 1) * 16u;
    const uint4* fl = frag + lane;

    #pragma unroll
    for (int ks = 0; ks < NK; ++ks) {
        // B fragments: 8 independent LDG.128 (L2-resident), issued first
        const uint4* fp = fl + ks * 256;
        uint4 bh0 = fp[0],   bh1 = fp[64],  bh2 = fp[128], bh3 = fp[192];
        uint4 bl0 = fp[32],  bl1 = fp[96],  bl2 = fp[160], bl3 = fp[224];

        uint32_t ah[2][4], al[2][4];
        uint32_t aa = a_base + (uint32_t)ks * 32u;
        ldsm4(ah[0], aa);
        ldsm4(ah[1], aa + 16u * ASTR);
        ldsm4(al[0], aa + (B_ALO - B_AHI));
        ldsm4(al[1], aa + 16u * ASTR + (B_ALO - B_AHI));

        // term 1: Ahi*Whi, term 2: Alo*Whi
        #pragma unroll
        for (int m = 0; m < 2; ++m) {
            mma16816(acc[m][0], ah[m], bh0.x, bh0.y);
            mma16816(acc[m][1], ah[m], bh0.z, bh0.w);
            mma16816(acc[m][2], ah[m], bh1.x, bh1.y);
            mma16816(acc[m][3], ah[m], bh1.z, bh1.w);
            mma16816(acc[m][4], ah[m], bh2.x, bh2.y);
            mma16816(acc[m][5], ah[m], bh2.z, bh2.w);
            mma16816(acc[m][6], ah[m], bh3.x, bh3.y);
            mma16816(acc[m][7], ah[m], bh3.z, bh3.w);
        }
        #pragma unroll
        for (int m = 0; m < 2; ++m) {
            mma16816(acc[m][0], al[m], bh0.x, bh0.y);
            mma16816(acc[m][1], al[m], bh0.z, bh0.w);
            mma16816(acc[m][2], al[m], bh1.x, bh1.y);
            mma16816(acc[m][3], al[m], bh1.z, bh1.w);
            mma16816(acc[m][4], al[m], bh2.x, bh2.y);
            mma16816(acc[m][5], al[m], bh2.z, bh2.w);
            mma16816(acc[m][6], al[m], bh3.x, bh3.y);
            mma16816(acc[m][7], al[m], bh3.z, bh3.w);
        }
        // term 3: Ahi*Wlo
        #pragma unroll
        for (int m = 0; m < 2; ++m) {
            mma16816(acc[m][0], ah[m], bl0.x, bl0.y);
            mma16816(acc[m][1], ah[m], bl0.z, bl0.w);
            mma16816(acc[m][2], ah[m], bl1.x, bl1.y);
            mma16816(acc[m][3], ah[m], bl1.z, bl1.w);
            mma16816(acc[m][4], ah[m], bl2.x, bl2.y);
            mma16816(acc[m][5], ah[m], bl2.z, bl2.w);
            mma16816(acc[m][6], ah[m], bl3.x, bl3.y);
            mma16816(acc[m][7], ah[m], bl3.z, bl3.w);
        }
    }

    __syncthreads();   // all mma reads of A complete before in-place A writes

    // epilogue: bias + (leaky)relu with value-row gating, split to bf16, store to A
    const int comp = (lane >> 2) & 3;
    const int vl   = lane & 19;
    const int colq = 2 * (lane & 3);

    #pragma unroll
    for (int m = 0; m < 2; ++m) {
        #pragma unroll
        for (int nt = 0; nt < 8; ++nt) {
            float* d = acc[m][nt];
            int j0 = n0 + nt * 8 + colq;
            float b0 = sBias[j0], b1 = sBias[j0 + 1];
            float q0 = d[0] + b0, q1 = d[1] + b1;
            float q2 = d[2] + b0, q3 = d[3] + b1;
            float m0 = __shfl_sync(0xffffffffu, q0, vl) > 0.f ? 1.f : slope;
            float m1 = __shfl_sync(0xffffffffu, q1, vl) > 0.f ? 1.f : slope;
            float m2 = __shfl_sync(0xffffffffu, q2, vl) > 0.f ? 1.f : slope;
            float m3 = __shfl_sync(0xffffffffu, q3, vl) > 0.f ? 1.f : slope;
            float o0 = m0 * (comp == 0 ? q0 : d[0]);
            float o1 = m1 * (comp == 0 ? q1 : d[1]);
            float o2 = m2 * (comp == 0 ? q2 : d[2]);
            float o3 = m3 * (comp == 0 ? q3 : d[3]);
            uint32_t h01, l01, h23, l23;
            split2(o0, o1, h01, l01);
            split2(o2, o3, h23, l23);
            uint32_t cA  = (uint32_t)(c0 + m * 16 + (lane >> 2));
            uint32_t off = cA * ASTR + (uint32_t)j0 * 2u;
            *(uint32_t*)(smem + B_AHI + off) = h01;
            *(uint32_t*)(smem + B_ALO + off) = l01;
            off += 8u * ASTR;
            *(uint32_t*)(smem + B_AHI + off) = h23;
            *(uint32_t*)(smem + B_ALO + off) = l23;
        }
    }
}

// ----------------------------------------------------------------
__global__ __launch_bounds__(THREADS, 1)
void nerfies_kernel(const float* __restrict__ x,
                    const float* __restrict__ bin,
                    const float* __restrict__ bs,
                    const float* __restrict__ Ww,
                    const float* __restrict__ bw,
                    const float* __restrict__ Wv,
                    const float* __restrict__ bv,
                    const int*   __restrict__ iter,
                    float* __restrict__ out,
                    int N)
{
    extern __shared__ __align__(16) char smem[];
    const uint32_t sb = smem_u32(smem);
    const int tid  = threadIdx.x;
    const int wid  = tid >> 5;
    const int lane = tid & 31;
    const int p0   = blockIdx.x * PTS;
    const int wn   = wid & 1;

    // zero A (hi+lo) regions (covers k-padding)
    {
        uint4 z = make_uint4(0, 0, 0, 0);
        for (uint32_t o = (uint32_t)tid * 16u; o < B_BIAS; o += THREADS * 16u)
            *(uint4*)(smem + o) = z;
    }

    // posenc (PI literal 3.14, N_ANNEAL = 3000, M=6, K0=-3)
    const float itf = (float)(*iter);
    const float aa  = 6.0f * itf / 3000.0f;
    __syncthreads();

    for (int idx = tid; idx < PTS * DIMX; idx += THREADS) {
        int p = idx / DIMX, f = idx % DIMX;
        int gp = p0 + p;
        float val = 0.f, d0 = 0.f, d1 = 0.f, d2 = 0.f;
        if (gp < N) {
            if (f < 3) {
                val = x[gp * 3 + f];
                if (f == 0) d0 = 1.f; else if (f == 1) d1 = 1.f; else d2 = 1.f;
            } else {
                int g = f - 3;
                int cdim = g / 12;
                int rem = g % 12;
                int t = rem / 6;
                int j = rem % 6;
                float wj = (1.0f - cosf(fminf(fmaxf(aa - (float)j, 0.f), 1.f) * 3.14f)) * 0.5f;
                float mj = exp2f((float)(j - 3)) * 3.14f;
                float xc = x[gp * 3 + cdim];
                float ang = xc * mj;
                float sv = sinf(ang), cv = cosf(ang);
                float dv;
                if (t == 0) { val = sv * wj; dv =  cv * mj * wj; }
                else        { val = cv * wj; dv = -sv * mj * wj; }
                if (cdim == 0) d0 = dv; else if (cdim == 1) d1 = dv; else d2 = dv;
            }
        }
        float vals[4] = {val, d0, d1, d2};
        #pragma unroll
        for (int d = 0; d < 4; ++d) {
            __nv_bfloat16 hh, ll;
            split_bf16(vals[d], hh, ll);
            uint32_t off = (uint32_t)(4 * p + d) * ASTR + (uint32_t)f * 2u;
            *(__nv_bfloat16*)(smem + B_AHI + off) = hh;
            *(__nv_bfloat16*)(smem + B_ALO + off) = ll;
        }
    }

    // all biases (input + 6 hidden) preloaded once
    for (int i = tid; i < 896; i += THREADS) {
        float v = (i < 128) ? bin[i] : bs[i - 128];
        ((float*)(smem + B_BIAS))[i] = v;
    }
    // head weights + biases
    for (int idx = tid; idx < 384; idx += THREADS) {
        ((float*)(smem + B_WW))[idx] = Ww[idx];
        ((float*)(smem + B_WV))[idx] = Wv[idx];
    }
    if (tid < 3) {
        ((float*)(smem + B_BH))[tid]     = bw[tid];
        ((float*)(smem + B_BH))[tid + 3] = bv[tid];
    }
    __syncthreads();

    // ---- layer 0: K padded 39->48 (3 ksteps), leaky_relu(0.01)
    layer_mma<3>(smem, sb, g_fragWin + wn * 768,
                 (const float*)(smem + B_BIAS), wid, lane, 0.01f);

    // ---- 6 hidden layers: K=128 (8 ksteps), relu
    for (int l = 0; l < NHID; ++l) {
        __syncthreads();   // epilogue A writes visible before next MMA reads
        layer_mma<8>(smem, sb, g_fragW + (size_t)(l * 2 + wn) * 2048,
                     (const float*)(smem + B_BIAS) + (1 + l) * 128, wid, lane, 0.f);
    }
    __syncthreads();       // final A writes visible to tail

    // ---- tail: heads (128->3 x2 with tangents), SE(3) exp, outputs ----
    const float* sWw = (const float*)(smem + B_WW);
    const float* sWv = (const float*)(smem + B_WV);
    const float* sBH = (const float*)(smem + B_BH);

    const int p  = tid >> 3;
    const int r  = tid & 7;
    const int gp = p0 + p;

    float aw[3][4], av[3][4];
    #pragma unroll
    for (int a = 0; a < 3; ++a)
        #pragma unroll
        for (int cc = 0; cc < 4; ++cc) { aw[a][cc] = 0.f; av[a][cc] = 0.f; }

    #pragma unroll
    for (int kc = 0; kc < 2; ++kc) {
        int k0 = r * 16 + kc * 8;
        float f[4][8];
        #pragma unroll
        for (int c4 = 0; c4 < 4; ++c4) {
            uint32_t off = (uint32_t)(4 * p + c4) * ASTR + (uint32_t)k0 * 2u;
            uint4 hh = *(const uint4*)(smem + B_AHI + off);
            uint4 ll = *(const uint4*)(smem + B_ALO + off);
            uint32_t hu[4] = {hh.x, hh.y, hh.z, hh.w};
            uint32_t lu[4] = {ll.x, ll.y, ll.z, ll.w};
            #pragma unroll
            for (int t = 0; t < 4; ++t) {
                f[c4][2*t]   = bflo(hu[t]) + bflo(lu[t]);
                f[c4][2*t+1] = bfhi(hu[t]) + bfhi(lu[t]);
            }
        }
        #pragma unroll
        for (int i = 0; i < 8; ++i) {
            int k = k0 + i;
            #pragma unroll
            for (int a = 0; a < 3; ++a) {
                float ww = sWw[a * HID + k];
                float wv = sWv[a * HID + k];
                #pragma unroll
                for (int cc = 0; cc < 4; ++cc) {
                    aw[a][cc] = fmaf(ww, f[cc][i], aw[a][cc]);
                    av[a][cc] = fmaf(wv, f[cc][i], av[a][cc]);
                }
            }
        }
    }
    #pragma unroll
    for (int off8 = 4; off8 >= 1; off8 >>= 1) {
        #pragma unroll
        for (int a = 0; a < 3; ++a)
            #pragma unroll
            for (int cc = 0; cc < 4; ++cc) {
                aw[a][cc] += __shfl_down_sync(0xffffffffu, aw[a][cc], off8, 8);
                av[a][cc] += __shfl_down_sync(0xffffffffu, av[a][cc], off8, 8);
            }
    }

    if (r == 0 && gp < N) {
        Dn wr[3], vr[3];
        #pragma unroll
        for (int a = 0; a < 3; ++a) {
            wr[a] = Dn{aw[a][0] + sBH[a],     aw[a][1], aw[a][2], aw[a][3]};
            vr[a] = Dn{av[a][0] + sBH[a + 3], av[a][1], av[a][2], av[a][3]};
        }
        Dn n2 = dadd(dadd(dmul(wr[0], wr[0]), dmul(wr[1], wr[1])), dmul(wr[2], wr[2]));
        Dn th = dsqrt(n2);
        Dn rt = drcp(th);
        Dn w0 = dmul(wr[0], rt), w1 = dmul(wr[1], rt), w2 = dmul(wr[2], rt);
        Dn v0 = dmul(vr[0], rt), v1 = dmul(vr[1], rt), v2 = dmul(vr[2], rt);
        Dn s  = dsin(th), c = dcos(th);
        Dn oc = dsub(dmk(1.f), c);
        Dn ts = dsub(th, s);

        Dn Wm[3][3] = {
            { dmk(0.f), dneg(w2),  w1       },
            { w2,       dmk(0.f),  dneg(w0) },
            { dneg(w1), w0,        dmk(0.f) } };
        Dn W2[3][3];
        #pragma unroll
        for (int i = 0; i < 3; ++i)
            #pragma unroll
            for (int j = 0; j < 3; ++j)
                W2[i][j] = dadd(dadd(dmul(Wm[i][0], Wm[0][j]),
                                     dmul(Wm[i][1], Wm[1][j])),
                                dmul(Wm[i][2], Wm[2][j]));
        Dn R[3][3], G[3][3];
        #pragma unroll
        for (int i = 0; i < 3; ++i)
            #pragma unroll
            for (int j = 0; j < 3; ++j) {
                Dn rr2 = dadd(dmul(s, Wm[i][j]), dmul(oc, W2[i][j]));
                if (i == j) rr2.v += 1.f;
                R[i][j] = rr2;
                Dn gg = dadd(dmul(oc, Wm[i][j]), dmul(ts, W2[i][j]));
                if (i == j) gg = dadd(gg, th);
                G[i][j] = gg;
            }
        Dn tvec[3];
        #pragma unroll
        for (int i = 0; i < 3; ++i)
            tvec[i] = dadd(dadd(dmul(G[i][0], v0), dmul(G[i][1], v1)), dmul(G[i][2], v2));

        float xv0 = x[gp * 3 + 0], xv1 = x[gp * 3 + 1], xv2 = x[gp * 3 + 2];
        Dn xd[3] = { Dn{xv0, 1.f, 0.f, 0.f}, Dn{xv1, 0.f, 1.f, 0.f}, Dn{xv2, 0.f, 0.f, 1.f} };

        float* J = out + (size_t)N * 3 + (size_t)gp * 9;
        #pragma unroll
        for (int i = 0; i < 3; ++i) {
            Dn o = dadd(tvec[i],
                        dadd(dadd(dmul(R[i][0], xd[0]), dmul(R[i][1], xd[1])),
                             dmul(R[i][2], xd[2])));
            out[gp * 3 + i] = o.v;
            J[i * 3 + 0] = o.x;
            J[i * 3 + 1] = o.y;
            J[i * 3 + 2] = o.z;
        }
    }
}

// ----------------------------------------------------------------
extern "C" void kernel_launch(void* const* d_in, const int* in_sizes, int n_in,
                              void* d_out, int out_size) {
    const float* x   = (const float*)d_in[0];
    const float* Win = (const float*)d_in[1];
    const float* bin = (const float*)d_in[2];
    const float* Ws  = (const float*)d_in[3];
    const float* bs  = (const float*)d_in[4];
    const float* Ww  = (const float*)d_in[5];
    const float* bw  = (const float*)d_in[6];
    const float* Wv  = (const float*)d_in[7];
    const float* bv  = (const float*)d_in[8];
    const int*   it  = (const int*)d_in[9];
    float* out = (float*)d_out;

    int N = in_sizes[0] / 3;
    int grid = (N + PTS - 1) / PTS;

    prep_kernel<<<(24576 + 1536 + 255) / 256, 256>>>(Win, Ws);

    cudaFuncSetAttribute(nerfies_kernel,
                         cudaFuncAttributeMaxDynamicSharedMemorySize, SMEM_BYTES);
    nerfies_kernel<<<grid, THREADS, SMEM_BYTES>>>(x, bin, bs, Ww, bw, Wv, bv,
                                                  it, out, N);
}

// round 16
// speedup vs baseline: 1.5527x; 1.0000x over previous
#include <cuda_runtime.h>
#include <cuda_bf16.h>
#include <stdint.h>

#define THREADS 512
#define PTS     64
#define HID     128
#define DIMX    39
#define NHID    6

// padded row stride (bytes) for A (256 rows): 128 bf16 + 8 pad
#define ASTR    272u

// smem byte offsets (A only + small constants)
#define B_AHI   0u
#define B_ALO   69632u      // 256*272
#define B_BIAS  139264u     // 7 x 128 f32 (input + 6 hidden)
#define B_WW    142848u     // 3x128 f32
#define B_WV    144384u
#define B_BH    145920u     // bw[3], bv[3]
#define SMEM_BYTES 145952u

// W fragments, pre-split to bf16 hi/lo in ldmatrix per-lane order.
// flat = (layer*2+wn)*2048 + ks*256 + (np*2+h)*32 + lane   (uint4 each)
__device__ uint4 g_fragW[24576];    // 6 layers * 2 wn * 2048
__device__ uint4 g_fragWin[1536];   // 2 wn * 3 ks * 256

// ---------------------------------------------------------------- PTX helpers
static __device__ __forceinline__ uint32_t smem_u32(const void* p){
    uint32_t a;
    asm("{ .reg .u64 t; cvta.to.shared.u64 t, %1; cvt.u32.u64 %0, t; }" : "=r"(a) : "l"(p));
    return a;
}
static __device__ __forceinline__ void ldsm4(uint32_t* r, uint32_t addr){
    asm volatile("ldmatrix.sync.aligned.m8n8.x4.shared.b16 {%0,%1,%2,%3}, [%4];"
        : "=r"(r[0]), "=r"(r[1]), "=r"(r[2]), "=r"(r[3]) : "r"(addr));
}
static __device__ __forceinline__ void mma16816(float* d, const uint32_t* a,
                                                uint32_t b0, uint32_t b1){
    asm volatile("mma.sync.aligned.m16n8k16.row.col.f32.bf16.bf16.f32 "
        "{%0,%1,%2,%3}, {%4,%5,%6,%7}, {%8,%9}, {%0,%1,%2,%3};"
        : "+f"(d[0]), "+f"(d[1]), "+f"(d[2]), "+f"(d[3])
        : "r"(a[0]), "r"(a[1]), "r"(a[2]), "r"(a[3]), "r"(b0), "r"(b1));
}

// split fp32 pair -> packed bf16 hi pair + lo pair
static __device__ __forceinline__ void split2(float f0, float f1, uint32_t& hp, uint32_t& lp){
    __nv_bfloat162 h = __floats2bfloat162_rn(f0, f1);
    hp = *(uint32_t*)&h;
    float fh0 = __uint_as_float(hp << 16);
    float fh1 = __uint_as_float(hp & 0xffff0000u);
    __nv_bfloat162 l = __floats2bfloat162_rn(f0 - fh0, f1 - fh1);
    lp = *(uint32_t*)&l;
}
static __device__ __forceinline__ void split_bf16(float v, __nv_bfloat16& h, __nv_bfloat16& l){
    h = __float2bfloat16(v);
    l = __float2bfloat16(v - __bfloat162float(h));
}
__device__ __forceinline__ float bflo(uint32_t u){ return __uint_as_float(u << 16); }
__device__ __forceinline__ float bfhi(uint32_t u){ return __uint_as_float(u & 0xffff0000u); }

// ---------------------------------------------------------------- dual numbers
struct Dn { float v, x, y, z; };
__device__ __forceinline__ Dn dmk(float v){ return Dn{v,0.f,0.f,0.f}; }
__device__ __forceinline__ Dn dadd(const Dn&a,const Dn&b){ return Dn{a.v+b.v,a.x+b.x,a.y+b.y,a.z+b.z}; }
__device__ __forceinline__ Dn dsub(const Dn&a,const Dn&b){ return Dn{a.v-b.v,a.x-b.x,a.y-b.y,a.z-b.z}; }
__device__ __forceinline__ Dn dneg(const Dn&a){ return Dn{-a.v,-a.x,-a.y,-a.z}; }
__device__ __forceinline__ Dn dmul(const Dn&a,const Dn&b){
    return Dn{a.v*b.v, fmaf(a.v,b.x,a.x*b.v), fmaf(a.v,b.y,a.y*b.v), fmaf(a.v,b.z,a.z*b.v)};
}
__device__ __forceinline__ Dn dsqrt(const Dn&a){ float s=sqrtf(a.v),h=0.5f/s; return Dn{s,a.x*h,a.y*h,a.z*h}; }
__device__ __forceinline__ Dn drcp(const Dn&a){ float r=1.f/a.v,m=-r*r; return Dn{r,a.x*m,a.y*m,a.z*m}; }
__device__ __forceinline__ Dn dsin(const Dn&a){ float s=sinf(a.v),c=cosf(a.v); return Dn{s,c*a.x,c*a.y,c*a.z}; }
__device__ __forceinline__ Dn dcos(const Dn&a){ float s=sinf(a.v),c=cosf(a.v); return Dn{c,-s*a.x,-s*a.y,-s*a.z}; }

// ---------------------------------------------------------------- prep kernel: W -> fragment-ordered bf16 hi/lo
// fragment reg i of lane l (warp wn, tile np, kstep ks):
//   j = wn*64 + np*16 + (l>>2) + ((i>>1)&1)*8
//   k = ks*16 + (i&1)*8 + 2*(l&3)      (pair k, k+1)
__global__ void prep_kernel(const float* __restrict__ Win, const float* __restrict__ Ws)
{
    int f = blockIdx.x * blockDim.x + threadIdx.x;
    if (f < 24576) {
        int lane = f & 31, h = (f >> 5) & 1, np = (f >> 6) & 3;
        int ks = (f >> 8) & 7, wn = (f >> 11) & 1, l = f >> 12;
        const float* W = Ws + (size_t)l * HID * HID;
        uint32_t r[4];
        #pragma unroll
        for (int i = 0; i < 4; ++i) {
            int j = wn * 64 + np * 16 + (lane >> 2) + ((i >> 1) & 1) * 8;
            int k = ks * 16 + (i & 1) * 8 + 2 * (lane & 3);
            float w0 = W[j * HID + k], w1 = W[j * HID + k + 1];
            uint32_t hp, lp;
            split2(w0, w1, hp, lp);
            r[i] = h ? lp : hp;
        }
        g_fragW[f] = make_uint4(r[0], r[1], r[2], r[3]);
    } else if (f < 24576 + 1536) {
        int f2 = f - 24576;
        int lane = f2 & 31, h = (f2 >> 5) & 1, np = (f2 >> 6) & 3;
        int ks = (f2 >> 8) % 3, wn = (f2 >> 8) / 3;
        uint32_t r[4];
        #pragma unroll
        for (int i = 0; i < 4; ++i) {
            int j = wn * 64 + np * 16 + (lane >> 2) + ((i >> 1) & 1) * 8;
            int k = ks * 16 + (i & 1) * 8 + 2 * (lane & 3);
            float w0 = (k     < DIMX) ? Win[j * DIMX + k]     : 0.f;
            float w1 = (k + 1 < DIMX) ? Win[j * DIMX + k + 1] : 0.f;
            uint32_t hp, lp;
            split2(w0, w1, hp, lp);
            r[i] = h ? lp : hp;
        }
        g_fragWin[f2] = make_uint4(r[0], r[1], r[2], r[3]);
    }
}

// ---------------------------------------------------------------- one MLP layer: B frags via LDG, A via LDSM
template<int NK>
__device__ __forceinline__ void layer_mma(char* smem, uint32_t sb,
                                          const uint4* __restrict__ frag,
                                          const float* __restrict__ sBias,
                                          int wid, int lane, float slope)
{
    const int wm = wid >> 1, wn = wid & 1;
    const int c0 = wm * 32, n0 = wn * 64;
    const int q  = lane >> 3, rr = lane & 7;

    float acc[2][8][4];
    #pragma unroll
    for (int m = 0; m < 2; ++m)
        #pragma unroll
        for (int nt = 0; nt < 8; ++nt)
            #pragma unroll
            for (int i = 0; i < 4; ++i) acc[m][nt][i] = 0.f;

    const uint32_t a_base = sb + B_AHI
        + (uint32_t)(c0 + rr + 8 * (q & 1)) * ASTR + (uint32_t)(q >> 1) * 16u;
    const uint4* fl = frag + lane;

    #pragma unroll
    for (int ks = 0; ks < NK; ++ks) {
        // B fragments: 8 independent LDG.128 (L2-resident), issued first
        const uint4* fp = fl + ks * 256;
        uint4 bh0 = fp[0],   bh1 = fp[64],  bh2 = fp[128], bh3 = fp[192];
        uint4 bl0 = fp[32],  bl1 = fp[96],  bl2 = fp[160], bl3 = fp[224];

        uint32_t ah[2][4], al[2][4];
        uint32_t aa = a_base + (uint32_t)ks * 32u;
        ldsm4(ah[0], aa);
        ldsm4(ah[1], aa + 16u * ASTR);
        ldsm4(al[0], aa + (B_ALO - B_AHI));
        ldsm4(al[1], aa + 16u * ASTR + (B_ALO - B_AHI));

        // term 1: Ahi*Whi, term 2: Alo*Whi
        #pragma unroll
        for (int m = 0; m < 2; ++m) {
            mma16816(acc[m][0], ah[m], bh0.x, bh0.y);
            mma16816(acc[m][1], ah[m], bh0.z, bh0.w);
            mma16816(acc[m][2], ah[m], bh1.x, bh1.y);
            mma16816(acc[m][3], ah[m], bh1.z, bh1.w);
            mma16816(acc[m][4], ah[m], bh2.x, bh2.y);
            mma16816(acc[m][5], ah[m], bh2.z, bh2.w);
            mma16816(acc[m][6], ah[m], bh3.x, bh3.y);
            mma16816(acc[m][7], ah[m], bh3.z, bh3.w);
        }
        #pragma unroll
        for (int m = 0; m < 2; ++m) {
            mma16816(acc[m][0], al[m], bh0.x, bh0.y);
            mma16816(acc[m][1], al[m], bh0.z, bh0.w);
            mma16816(acc[m][2], al[m], bh1.x, bh1.y);
            mma16816(acc[m][3], al[m], bh1.z, bh1.w);
            mma16816(acc[m][4], al[m], bh2.x, bh2.y);
            mma16816(acc[m][5], al[m], bh2.z, bh2.w);
            mma16816(acc[m][6], al[m], bh3.x, bh3.y);
            mma16816(acc[m][7], al[m], bh3.z, bh3.w);
        }
        // term 3: Ahi*Wlo
        #pragma unroll
        for (int m = 0; m < 2; ++m) {
            mma16816(acc[m][0], ah[m], bl0.x, bl0.y);
            mma16816(acc[m][1], ah[m], bl0.z, bl0.w);
            mma16816(acc[m][2], ah[m], bl1.x, bl1.y);
            mma16816(acc[m][3], ah[m], bl1.z, bl1.w);
            mma16816(acc[m][4], ah[m], bl2.x, bl2.y);
            mma16816(acc[m][5], ah[m], bl2.z, bl2.w);
            mma16816(acc[m][6], ah[m], bl3.x, bl3.y);
            mma16816(acc[m][7], ah[m], bl3.z, bl3.w);
        }
    }

    __syncthreads();   // all mma reads of A complete before in-place A writes

    // epilogue: bias + (leaky)relu with value-row gating, split to bf16, store to A
    const int comp = (lane >> 2) & 3;
    const int vl   = lane & 19;
    const int colq = 2 * (lane & 3);

    #pragma unroll
    for (int m = 0; m < 2; ++m) {
        #pragma unroll
        for (int nt = 0; nt < 8; ++nt) {
            float* d = acc[m][nt];
            int j0 = n0 + nt * 8 + colq;
            float b0 = sBias[j0], b1 = sBias[j0 + 1];
            float q0 = d[0] + b0, q1 = d[1] + b1;
            float q2 = d[2] + b0, q3 = d[3] + b1;
            float m0 = __shfl_sync(0xffffffffu, q0, vl) > 0.f ? 1.f : slope;
            float m1 = __shfl_sync(0xffffffffu, q1, vl) > 0.f ? 1.f : slope;
            float m2 = __shfl_sync(0xffffffffu, q2, vl) > 0.f ? 1.f : slope;
            float m3 = __shfl_sync(0xffffffffu, q3, vl) > 0.f ? 1.f : slope;
            float o0 = m0 * (comp == 0 ? q0 : d[0]);
            float o1 = m1 * (comp == 0 ? q1 : d[1]);
            float o2 = m2 * (comp == 0 ? q2 : d[2]);
            float o3 = m3 * (comp == 0 ? q3 : d[3]);
            uint32_t h01, l01, h23, l23;
            split2(o0, o1, h01, l01);
            split2(o2, o3, h23, l23);
            uint32_t cA  = (uint32_t)(c0 + m * 16 + (lane >> 2));
            uint32_t off = cA * ASTR + (uint32_t)j0 * 2u;
            *(uint32_t*)(smem + B_AHI + off) = h01;
            *(uint32_t*)(smem + B_ALO + off) = l01;
            off += 8u * ASTR;
            *(uint32_t*)(smem + B_AHI + off) = h23;
            *(uint32_t*)(smem + B_ALO + off) = l23;
        }
    }
}

// ----------------------------------------------------------------
__global__ __launch_bounds__(THREADS, 1)
void nerfies_kernel(const float* __restrict__ x,
                    const float* __restrict__ bin,
                    const float* __restrict__ bs,
                    const float* __restrict__ Ww,
                    const float* __restrict__ bw,
                    const float* __restrict__ Wv,
                    const float* __restrict__ bv,
                    const int*   __restrict__ iter,
                    float* __restrict__ out,
                    int N)
{
    extern __shared__ __align__(16) char smem[];
    const uint32_t sb = smem_u32(smem);
    const int tid  = threadIdx.x;
    const int wid  = tid >> 5;
    const int lane = tid & 31;
    const int p0   = blockIdx.x * PTS;
    const int wn   = wid & 1;

    // zero A (hi+lo) regions (covers k-padding)
    {
        uint4 z = make_uint4(0, 0, 0, 0);
        for (uint32_t o = (uint32_t)tid * 16u; o < B_BIAS; o += THREADS * 16u)
            *(uint4*)(smem + o) = z;
    }

    // posenc (PI literal 3.14, N_ANNEAL = 3000, M=6, K0=-3)
    const float itf = (float)(*iter);
    const float aa  = 6.0f * itf / 3000.0f;
    __syncthreads();

    for (int idx = tid; idx < PTS * DIMX; idx += THREADS) {
        int p = idx / DIMX, f = idx % DIMX;
        int gp = p0 + p;
        float val = 0.f, d0 = 0.f, d1 = 0.f, d2 = 0.f;
        if (gp < N) {
            if (f < 3) {
                val = x[gp * 3 + f];
                if (f == 0) d0 = 1.f; else if (f == 1) d1 = 1.f; else d2 = 1.f;
            } else {
                int g = f - 3;
                int cdim = g / 12;
                int rem = g % 12;
                int t = rem / 6;
                int j = rem % 6;
                float wj = (1.0f - cosf(fminf(fmaxf(aa - (float)j, 0.f), 1.f) * 3.14f)) * 0.5f;
                float mj = exp2f((float)(j - 3)) * 3.14f;
                float xc = x[gp * 3 + cdim];
                float ang = xc * mj;
                float sv = sinf(ang), cv = cosf(ang);
                float dv;
                if (t == 0) { val = sv * wj; dv =  cv * mj * wj; }
                else        { val = cv * wj; dv = -sv * mj * wj; }
                if (cdim == 0) d0 = dv; else if (cdim == 1) d1 = dv; else d2 = dv;
            }
        }
        float vals[4] = {val, d0, d1, d2};
        #pragma unroll
        for (int d = 0; d < 4; ++d) {
            __nv_bfloat16 hh, ll;
            split_bf16(vals[d], hh, ll);
            uint32_t off = (uint32_t)(4 * p + d) * ASTR + (uint32_t)f * 2u;
            *(__nv_bfloat16*)(smem + B_AHI + off) = hh;
            *(__nv_bfloat16*)(smem + B_ALO + off) = ll;
        }
    }

    // all biases (input + 6 hidden) preloaded once
    for (int i = tid; i < 896; i += THREADS) {
        float v = (i < 128) ? bin[i] : bs[i - 128];
        ((float*)(smem + B_BIAS))[i] = v;
    }
    // head weights + biases
    for (int idx = tid; idx < 384; idx += THREADS) {
        ((float*)(smem + B_WW))[idx] = Ww[idx];
        ((float*)(smem + B_WV))[idx] = Wv[idx];
    }
    if (tid < 3) {
        ((float*)(smem + B_BH))[tid]     = bw[tid];
        ((float*)(smem + B_BH))[tid + 3] = bv[tid];
    }
    __syncthreads();

    // ---- layer 0: K padded 39->48 (3 ksteps), leaky_relu(0.01)
    layer_mma<3>(smem, sb, g_fragWin + wn * 768,
                 (const float*)(smem + B_BIAS), wid, lane, 0.01f);

    // ---- 6 hidden layers: K=128 (8 ksteps), relu
    for (int l = 0; l < NHID; ++l) {
        __syncthreads();   // epilogue A writes visible before next MMA reads
        layer_mma<8>(smem, sb, g_fragW + (size_t)(l * 2 + wn) * 2048,
                     (const float*)(smem + B_BIAS) + (1 + l) * 128, wid, lane, 0.f);
    }
    __syncthreads();       // final A writes visible to tail

    // ---- tail: heads (128->3 x2 with tangents), SE(3) exp, outputs ----
    const float* sWw = (const float*)(smem + B_WW);
    const float* sWv = (const float*)(smem + B_WV);
    const float* sBH = (const float*)(smem + B_BH);

    const int p  = tid >> 3;
    const int r  = tid & 7;
    const int gp = p0 + p;

    float aw[3][4], av[3][4];
    #pragma unroll
    for (int a = 0; a < 3; ++a)
        #pragma unroll
        for (int cc = 0; cc < 4; ++cc) { aw[a][cc] = 0.f; av[a][cc] = 0.f; }

    #pragma unroll
    for (int kc = 0; kc < 2; ++kc) {
        int k0 = r * 16 + kc * 8;
        float f[4][8];
        #pragma unroll
        for (int c4 = 0; c4 < 4; ++c4) {
            uint32_t off = (uint32_t)(4 * p + c4) * ASTR + (uint32_t)k0 * 2u;
            uint4 hh = *(const uint4*)(smem + B_AHI + off);
            uint4 ll = *(const uint4*)(smem + B_ALO + off);
            uint32_t hu[4] = {hh.x, hh.y, hh.z, hh.w};
            uint32_t lu[4] = {ll.x, ll.y, ll.z, ll.w};
            #pragma unroll
            for (int t = 0; t < 4; ++t) {
                f[c4][2*t]   = bflo(hu[t]) + bflo(lu[t]);
                f[c4][2*t+1] = bfhi(hu[t]) + bfhi(lu[t]);
            }
        }
        #pragma unroll
        for (int i = 0; i < 8; ++i) {
            int k = k0 + i;
            #pragma unroll
            for (int a = 0; a < 3; ++a) {
                float ww = sWw[a * HID + k];
                float wv = sWv[a * HID + k];
                #pragma unroll
                for (int cc = 0; cc < 4; ++cc) {
                    aw[a][cc] = fmaf(ww, f[cc][i], aw[a][cc]);
                    av[a][cc] = fmaf(wv, f[cc][i], av[a][cc]);
                }
            }
        }
    }
    #pragma unroll
    for (int off8 = 4; off8 >= 1; off8 >>= 1) {
        #pragma unroll
        for (int a = 0; a < 3; ++a)
            #pragma unroll
            for (int cc = 0; cc < 4; ++cc) {
                aw[a][cc] += __shfl_down_sync(0xffffffffu, aw[a][cc], off8, 8);
                av[a][cc] += __shfl_down_sync(0xffffffffu, av[a][cc], off8, 8);
            }
    }

    if (r == 0 && gp < N) {
        Dn wr[3], vr[3];
        #pragma unroll
        for (int a = 0; a < 3; ++a) {
            wr[a] = Dn{aw[a][0] + sBH[a],     aw[a][1], aw[a][2], aw[a][3]};
            vr[a] = Dn{av[a][0] + sBH[a + 3], av[a][1], av[a][2], av[a][3]};
        }
        Dn n2 = dadd(dadd(dmul(wr[0], wr[0]), dmul(wr[1], wr[1])), dmul(wr[2], wr[2]));
        Dn th = dsqrt(n2);
        Dn rt = drcp(th);
        Dn w0 = dmul(wr[0], rt), w1 = dmul(wr[1], rt), w2 = dmul(wr[2], rt);
        Dn v0 = dmul(vr[0], rt), v1 = dmul(vr[1], rt), v2 = dmul(vr[2], rt);
        Dn s  = dsin(th), c = dcos(th);
        Dn oc = dsub(dmk(1.f), c);
        Dn ts = dsub(th, s);

        Dn Wm[3][3] = {
            { dmk(0.f), dneg(w2),  w1       },
            { w2,       dmk(0.f),  dneg(w0) },
            { dneg(w1), w0,        dmk(0.f) } };
        Dn W2[3][3];
        #pragma unroll
        for (int i = 0; i < 3; ++i)
            #pragma unroll
            for (int j = 0; j < 3; ++j)
                W2[i][j] = dadd(dadd(dmul(Wm[i][0], Wm[0][j]),
                                     dmul(Wm[i][1], Wm[1][j])),
                                dmul(Wm[i][2], Wm[2][j]));
        Dn R[3][3], G[3][3];
        #pragma unroll
        for (int i = 0; i < 3; ++i)
            #pragma unroll
            for (int j = 0; j < 3; ++j) {
                Dn rr2 = dadd(dmul(s, Wm[i][j]), dmul(oc, W2[i][j]));
                if (i == j) rr2.v += 1.f;
                R[i][j] = rr2;
                Dn gg = dadd(dmul(oc, Wm[i][j]), dmul(ts, W2[i][j]));
                if (i == j) gg = dadd(gg, th);
                G[i][j] = gg;
            }
        Dn tvec[3];
        #pragma unroll
        for (int i = 0; i < 3; ++i)
            tvec[i] = dadd(dadd(dmul(G[i][0], v0), dmul(G[i][1], v1)), dmul(G[i][2], v2));

        float xv0 = x[gp * 3 + 0], xv1 = x[gp * 3 + 1], xv2 = x[gp * 3 + 2];
        Dn xd[3] = { Dn{xv0, 1.f, 0.f, 0.f}, Dn{xv1, 0.f, 1.f, 0.f}, Dn{xv2, 0.f, 0.f, 1.f} };

        float* J = out + (size_t)N * 3 + (size_t)gp * 9;
        #pragma unroll
        for (int i = 0; i < 3; ++i) {
            Dn o = dadd(tvec[i],
                        dadd(dadd(dmul(R[i][0], xd[0]), dmul(R[i][1], xd[1])),
                             dmul(R[i][2], xd[2])));
            out[gp * 3 + i] = o.v;
            J[i * 3 + 0] = o.x;
            J[i * 3 + 1] = o.y;
            J[i * 3 + 2] = o.z;
        }
    }
}

// ----------------------------------------------------------------
extern "C" void kernel_launch(void* const* d_in, const int* in_sizes, int n_in,
                              void* d_out, int out_size) {
    const float* x   = (const float*)d_in[0];
    const float* Win = (const float*)d_in[1];
    const float* bin = (const float*)d_in[2];
    const float* Ws  = (const float*)d_in[3];
    const float* bs  = (const float*)d_in[4];
    const float* Ww  = (const float*)d_in[5];
    const float* bw  = (const float*)d_in[6];
    const float* Wv  = (const float*)d_in[7];
    const float* bv  = (const float*)d_in[8];
    const int*   it  = (const int*)d_in[9];
    float* out = (float*)d_out;

    int N = in_sizes[0] / 3;
    int grid = (N + PTS - 1) / PTS;

    prep_kernel<<<(24576 + 1536 + 255) / 256, 256>>>(Win, Ws);

    cudaFuncSetAttribute(nerfies_kernel,
                         cudaFuncAttributeMaxDynamicSharedMemorySize, SMEM_BYTES);
    nerfies_kernel<<<grid, THREADS, SMEM_BYTES>>>(x, bin, bs, Ww, bw, Wv, bv,
                                                  it, out, N);
}